// round 16
// baseline (speedup 1.0000x reference)
#include <cuda_runtime.h>
#include <cstdint>

#define NNODES 4096
#define NG     8
#define MPER   512
#define NW     16   // 512 bits = 16 uint32 words per row (block-local columns)
#define NBLK   128
#define NTHR   1024

// Scratch (no allocation allowed -> device globals)
__device__ uint32_t g_mask[NNODES * NW];   // A bitmask, block-local columns
__device__ int      g_deg[NNODES];
__device__ float    g_feat[7 * NNODES];    // feature-major [7][4096]
__device__ unsigned g_bar_grp[NG] = {};    // per-graph group barrier (monotonic)
__device__ unsigned g_exit = 0;            // exit counter for reset

struct U64x4 { unsigned long long a, b, c, d; };
__device__ __forceinline__ U64x4 ldg32(const float* p) {
    U64x4 v;
    asm volatile("ld.global.nc.v4.u64 {%0,%1,%2,%3}, [%4];"
                 : "=l"(v.a), "=l"(v.b), "=l"(v.c), "=l"(v.d) : "l"(p));
    return v;
}
// 8 nonzero-flags from 4 u64 (A holds only 0.0f/1.0f -> bit-pattern test exact)
__device__ __forceinline__ uint32_t flags8(const U64x4& v) {
    uint32_t r = 0;
    r |= (uint32_t)((unsigned)(v.a)        != 0u) << 0;
    r |= (uint32_t)((unsigned)(v.a >> 32)  != 0u) << 1;
    r |= (uint32_t)((unsigned)(v.b)        != 0u) << 2;
    r |= (uint32_t)((unsigned)(v.b >> 32)  != 0u) << 3;
    r |= (uint32_t)((unsigned)(v.c)        != 0u) << 4;
    r |= (uint32_t)((unsigned)(v.c >> 32)  != 0u) << 5;
    r |= (uint32_t)((unsigned)(v.d)        != 0u) << 6;
    r |= (uint32_t)((unsigned)(v.d >> 32)  != 0u) << 7;
    return r;
}

// group barrier over the 16 blocks of graph g (targets 16, then 32)
// release/acquire semantics (no MEMBAR.GPU drain)
__device__ __forceinline__ void group_barrier(int g, unsigned target) {
    __syncthreads();
    if (threadIdx.x == 0) {
        unsigned* addr = &g_bar_grp[g];
        asm volatile("red.release.gpu.global.add.u32 [%0], 1;" :: "l"(addr) : "memory");
        unsigned v;
        do {
            asm volatile("ld.acquire.gpu.global.u32 %0, [%1];" : "=r"(v) : "l"(addr) : "memory");
        } while (v < target);
    }
    __syncthreads();
}

__device__ __forceinline__ void barL() {   // named barrier 1: warps 0..15
    asm volatile("bar.sync 1, 512;" ::: "memory");
}
__device__ __forceinline__ void barU() {   // named barrier 2: warps 16..31
    asm volatile("bar.sync 2, 512;" ::: "memory");
}

__device__ __forceinline__ float warp_sum(float v) {
    #pragma unroll
    for (int o = 16; o; o >>= 1) v += __shfl_down_sync(0xffffffffu, v, o);
    return v;
}

// ---------------------------------------------------------------------------
// ONE kernel, 128 co-resident blocks x 1024 threads; per-graph pipelines.
// ---------------------------------------------------------------------------
__global__ void __launch_bounds__(NTHR) fused_kernel(const float* __restrict__ A,
                                                     float* __restrict__ out) {
    __shared__ uint32_t smask[MPER * NW];   // 32 KB (rowstats)
    __shared__ int      sdeg[MPER];
    __shared__ uint32_t sdegp[MPER / 4];
    __shared__ float    sh[MPER];           // stats (lower warps)
    __shared__ float    r1[16], r2[16], r3[16], r4[16];   // stats (upper warps / f3)
    __shared__ float    bcast;

    int b = blockIdx.x;
    int t = threadIdx.x;
    int warp = t >> 5, lane = t & 31;
    int grp  = b >> 4;          // graph
    int mem  = b & 15;          // member within group
    int lo   = grp << 9;

    // ======================= Phase 0: pack (warp per row) =======================
    {
        int n = b * 32 + warp;                 // rows of graph grp
        long base = (long)n * NNODES + ((long)grp << 9);
        U64x4 v0 = ldg32(A + base + 16 * lane);
        U64x4 v1 = ldg32(A + base + 16 * lane + 8);

        uint32_t h = flags8(v0) | (flags8(v1) << 8);    // 16 bits per lane
        int deg = __popc(h);
        uint32_t w = h | (__shfl_down_sync(0xffffffffu, h, 1) << 16);
        if ((lane & 1) == 0)
            g_mask[n * NW + (lane >> 1)] = w;

        #pragma unroll
        for (int o = 16; o; o >>= 1) deg += __shfl_down_sync(0xffffffffu, deg, o);
        if (lane == 0) g_deg[n] = deg;
    }

    group_barrier(grp, 16);

    // ================= Phase 1: rowstats (warp per row, split halves) =================
    {
        const uint4* src = reinterpret_cast<const uint4*>(&g_mask[lo * NW]);
        uint4*       dst = reinterpret_cast<uint4*>(smask);
        #pragma unroll
        for (int i = 0; i < 2; i++) dst[t + 1024 * i] = src[t + 1024 * i];
        if (t < 512) sdeg[t] = g_deg[lo + t];
        __syncthreads();
        if (t < 128) {
            sdegp[t] = (uint32_t)sdeg[4 * t]
                     | ((uint32_t)sdeg[4 * t + 1] << 8)
                     | ((uint32_t)sdeg[4 * t + 2] << 16)
                     | ((uint32_t)sdeg[4 * t + 3] << 24);
        }
        __syncthreads();

        int l    = lane & 15;            // owned word index
        int half = lane >> 4;            // 0/1: neighbor subset
        int nl   = mem * 32 + warp;      // local row

        uint32_t mw = smask[nl * NW + l];
        uint32_t diagbit = (l == (nl >> 5)) ? (1u << (nl & 31)) : 0u;
        mw |= diagbit;

        // batch all 8 broadcast shfls up front (independent; pipeline them)
        int srcbase = (lane & 16) | ((lane & 16) >> 1);  // half*24? no: half*8 within shfl idx
        uint32_t bw[8];
        #pragma unroll
        for (int w2 = 0; w2 < 8; w2++)
            bw[w2] = __shfl_sync(0xffffffffu, mw, ((lane >> 4) << 3) | w2);

        uint32_t m2 = 0;
        int f4r = 0;
        int kbase = (lane >> 4) << 8;    // half 0 -> bits 0..255, half 1 -> 256..511

        #pragma unroll 1
        for (int w2 = 0; w2 < 8; w2++) {
            uint32_t bits = bw[w2];
            int kb = kbase + w2 * 32;
            while (bits) {
                int k = kb + __ffs(bits) - 1;
                bits &= bits - 1;
                uint32_t rk = smask[k * NW + l];
                m2 |= rk;
                f4r += __popc(rk & mw);
            }
        }
        m2 |= __shfl_xor_sync(0xffffffffu, m2, 16);

        int m2cnt = __popc(m2);
        uint32_t aw = mw & ~diagbit;
        int f2num = 0;
        {
            uint32_t bits = aw;
            while (bits) {
                int bb = __ffs(bits) - 1;
                bits &= bits - 1;
                f2num += sdeg[l * 32 + bb];
            }
        }
        int m2deg;
        {
            const uint4* sp4 = reinterpret_cast<const uint4*>(sdegp);
            uint4 q0 = sp4[l * 2], q1 = sp4[l * 2 + 1];
            uint32_t dq[8] = {q0.x, q0.y, q0.z, q0.w, q1.x, q1.y, q1.z, q1.w};
            unsigned acc = 0u;
            #pragma unroll
            for (int j = 0; j < 8; j++) {
                uint32_t spread = (((m2 >> (4 * j)) & 0xFu) * 0x00204081u) & 0x01010101u;
                acc = __dp4a(spread, dq[j], acc);
            }
            m2deg = (int)acc;
        }

        // pack m2cnt (hi) + f2num (lo) into one reduce chain (sums < 2^20)
        int pk = (m2cnt << 20) | f2num;
        #pragma unroll
        for (int o = 16; o; o >>= 1) f4r += __shfl_down_sync(0xffffffffu, f4r, o);
        #pragma unroll
        for (int o = 8; o; o >>= 1) {
            pk    += __shfl_down_sync(0xffffffffu, pk,    o, 16);
            m2deg += __shfl_down_sync(0xffffffffu, m2deg, o, 16);
        }
        m2cnt = pk >> 20;
        f2num = pk & 0xFFFFF;

        if (lane == 0) {
            int   n   = lo + nl;
            float deg = (float)sdeg[nl];
            float f1v = 0.0f;
            if (deg > 1.0f) f1v = 2.0f * ((float)f4r - deg) / (deg * (deg - 1.0f));
            float f2v = (deg > 0.0f) ? (float)f2num / deg : 0.0f;
            float f4v = 0.5f * (float)f4r;
            float f5v = (float)m2deg - 2.0f * (float)f4r;
            float f6v = (float)m2cnt - deg - 1.0f;
            g_feat[0 * NNODES + n] = deg;
            g_feat[1 * NNODES + n] = f1v;
            g_feat[2 * NNODES + n] = f2v;
            g_feat[4 * NNODES + n] = f4v;
            g_feat[5 * NNODES + n] = f5v;
            g_feat[6 * NNODES + n] = f6v;
        }
    }

    group_barrier(grp, 32);

    // ====== Phase 2: stats (members 0..6 of each group) ======
    if (mem < 7) {
        int f = mem;

        if (f != 3 && warp >= 16) {
            // ---- upper warps: mean + central moments ----
            int tt = t - 512;
            int wu = warp - 16;
            float x = g_feat[f * NNODES + lo + tt];

            float s = warp_sum(x);
            if (lane == 0) r1[wu] = s;
            barU();
            if (wu == 0) {
                float v = (lane < 16) ? r1[lane] : 0.0f;
                #pragma unroll
                for (int o = 8; o; o >>= 1) v += __shfl_down_sync(0xffffffffu, v, o);
                if (lane == 0) bcast = v * (1.0f / MPER);
            }
            barU();
            float mean = bcast;

            float c  = x - mean;
            float c2 = c * c, c3 = c2 * c, c4 = c2 * c2;
            float s2 = warp_sum(c2), s3 = warp_sum(c3), s4 = warp_sum(c4);
            if (lane == 0) { r2[wu] = s2; r3[wu] = s3; r4[wu] = s4; }
            barU();
            if (wu == 0) {
                float v2 = (lane < 16) ? r2[lane] : 0.0f;
                float v3 = (lane < 16) ? r3[lane] : 0.0f;
                float v4 = (lane < 16) ? r4[lane] : 0.0f;
                #pragma unroll
                for (int o = 8; o; o >>= 1) {
                    v2 += __shfl_down_sync(0xffffffffu, v2, o);
                    v3 += __shfl_down_sync(0xffffffffu, v3, o);
                    v4 += __shfl_down_sync(0xffffffffu, v4, o);
                }
                if (lane == 0) {
                    float m2 = v2 * (1.0f / MPER);
                    float m3 = v3 * (1.0f / MPER);
                    float m4 = v4 * (1.0f / MPER);
                    float eps = 1e-4f;
                    float sd   = sqrtf(m2);
                    float skew = m3 / fmaxf(m2 * sd, eps);
                    float kurt = m4 / fmaxf(m2 * m2, eps);
                    out[grp * 35 +  0 + f] = mean;
                    out[grp * 35 + 14 + f] = sd;
                    out[grp * 35 + 21 + f] = skew;
                    out[grp * 35 + 28 + f] = kurt;
                }
            }
        } else if (f != 3 && warp < 16) {
            // ---- lower warps: median only (hybrid bitonic) ----
            float x = g_feat[f * NNODES + lo + t];
            #pragma unroll 1
            for (int k = 2; k <= MPER; k <<= 1) {
                bool dirUp = ((t & k) == 0);
                #pragma unroll 1
                for (int j = k >> 1; j >= 32; j >>= 1) {
                    barL();
                    sh[t] = x;
                    barL();
                    float other = sh[t ^ j];
                    bool amLow = ((t & j) == 0);
                    x = (dirUp == amLow) ? fminf(x, other) : fmaxf(x, other);
                }
                int j0 = (k >> 1 < 16) ? (k >> 1) : 16;
                #pragma unroll 1
                for (int j = j0; j >= 1; j >>= 1) {
                    float other = __shfl_xor_sync(0xffffffffu, x, j);
                    bool amLow = ((t & j) == 0);
                    x = (dirUp == amLow) ? fminf(x, other) : fmaxf(x, other);
                }
            }
            if (t == (MPER - 1) / 2) out[grp * 35 + 7 + f] = x;
        } else if (f == 3 && warp < 16) {
            // ---- f3: full pipeline in lower warps ----
            sh[t] = g_feat[1 * NNODES + lo + t];
            barL();
            int n = lo + t;
            float s = 0.0f;
            const uint4* rm = reinterpret_cast<const uint4*>(&g_mask[n * NW]);
            #pragma unroll
            for (int q = 0; q < 4; q++) {
                uint4 u = rm[q];
                uint32_t ws[4] = {u.x, u.y, u.z, u.w};
                #pragma unroll
                for (int j = 0; j < 4; j++) {
                    uint32_t bits = ws[j];
                    int base = (q * 4 + j) * 32;
                    while (bits) {
                        int v = base + __ffs(bits) - 1;
                        bits &= bits - 1;
                        s += sh[v];
                    }
                }
            }
            float deg = (float)g_deg[n];
            float x = (deg > 0.0f) ? s / deg : 0.0f;
            barL();

            // mean
            float s1 = warp_sum(x);
            if (lane == 0) r1[warp] = s1;
            barL();
            if (warp == 0) {
                float v = (lane < 16) ? r1[lane] : 0.0f;
                #pragma unroll
                for (int o = 8; o; o >>= 1) v += __shfl_down_sync(0xffffffffu, v, o);
                if (lane == 0) bcast = v * (1.0f / MPER);
            }
            barL();
            float mean = bcast;

            float c  = x - mean;
            float c2 = c * c, c3 = c2 * c, c4 = c2 * c2;
            float s2 = warp_sum(c2), s3 = warp_sum(c3), s4 = warp_sum(c4);
            if (lane == 0) { r2[warp] = s2; r3[warp] = s3; r4[warp] = s4; }
            barL();
            if (warp == 0) {
                float v2 = (lane < 16) ? r2[lane] : 0.0f;
                float v3 = (lane < 16) ? r3[lane] : 0.0f;
                float v4 = (lane < 16) ? r4[lane] : 0.0f;
                #pragma unroll
                for (int o = 8; o; o >>= 1) {
                    v2 += __shfl_down_sync(0xffffffffu, v2, o);
                    v3 += __shfl_down_sync(0xffffffffu, v3, o);
                    v4 += __shfl_down_sync(0xffffffffu, v4, o);
                }
                if (lane == 0) {
                    float m2 = v2 * (1.0f / MPER);
                    float m3 = v3 * (1.0f / MPER);
                    float m4 = v4 * (1.0f / MPER);
                    float eps = 1e-4f;
                    float sd   = sqrtf(m2);
                    float skew = m3 / fmaxf(m2 * sd, eps);
                    float kurt = m4 / fmaxf(m2 * m2, eps);
                    out[grp * 35 +  0 + f] = mean;
                    out[grp * 35 + 14 + f] = sd;
                    out[grp * 35 + 21 + f] = skew;
                    out[grp * 35 + 28 + f] = kurt;
                }
            }

            // median
            #pragma unroll 1
            for (int k = 2; k <= MPER; k <<= 1) {
                bool dirUp = ((t & k) == 0);
                #pragma unroll 1
                for (int j = k >> 1; j >= 32; j >>= 1) {
                    barL();
                    sh[t] = x;
                    barL();
                    float other = sh[t ^ j];
                    bool amLow = ((t & j) == 0);
                    x = (dirUp == amLow) ? fminf(x, other) : fmaxf(x, other);
                }
                int j0 = (k >> 1 < 16) ? (k >> 1) : 16;
                #pragma unroll 1
                for (int j = j0; j >= 1; j >>= 1) {
                    float other = __shfl_xor_sync(0xffffffffu, x, j);
                    bool amLow = ((t & j) == 0);
                    x = (dirUp == amLow) ? fminf(x, other) : fmaxf(x, other);
                }
            }
            if (t == (MPER - 1) / 2) out[grp * 35 + 7 + f] = x;
        }
    }

    // ======================= Exit: reset barrier state =======================
    // No block-wide sync needed: only thread 0 touches barrier state, and its
    // own polls completed before reaching here; g_exit gates the global reset.
    if (t == 0) {
        unsigned v = atomicAdd(&g_exit, 1u);
        if (v == NBLK - 1) {                 // last block out resets for next launch
            #pragma unroll
            for (int i = 0; i < NG; i++) *(volatile unsigned*)&g_bar_grp[i] = 0u;
            *(volatile unsigned*)&g_exit = 0u;
            __threadfence();
        }
    }
}

// ---------------------------------------------------------------------------
extern "C" void kernel_launch(void* const* d_in, const int* in_sizes, int n_in,
                              void* d_out, int out_size) {
    const float* A = (const float*)d_in[0];
    float* out = (float*)d_out;
    fused_kernel<<<NBLK, NTHR>>>(A, out);
}

// round 17
// speedup vs baseline: 1.1216x; 1.1216x over previous
#include <cuda_runtime.h>
#include <cstdint>

#define NNODES 4096
#define NG     8
#define MPER   512
#define NW     16   // 512 bits = 16 uint32 words per row (block-local columns)
#define NBLK   128
#define NTHR   1024

// Scratch (no allocation allowed -> device globals)
__device__ uint32_t g_mask[NNODES * NW];   // A bitmask, block-local columns
__device__ int      g_deg[NNODES];
__device__ float    g_feat[7 * NNODES];    // feature-major [7][4096]
__device__ unsigned g_bar_grp[NG] = {};    // per-graph group barrier (monotonic)
__device__ unsigned g_exit = 0;            // exit counter for reset

struct U64x4 { unsigned long long a, b, c, d; };
__device__ __forceinline__ U64x4 ldg32(const float* p) {
    U64x4 v;
    asm volatile("ld.global.nc.v4.u64 {%0,%1,%2,%3}, [%4];"
                 : "=l"(v.a), "=l"(v.b), "=l"(v.c), "=l"(v.d) : "l"(p));
    return v;
}
// 8 nonzero-flags from 4 u64 (A holds only 0.0f/1.0f -> bit-pattern test exact)
__device__ __forceinline__ uint32_t flags8(const U64x4& v) {
    uint32_t r = 0;
    r |= (uint32_t)((unsigned)(v.a)        != 0u) << 0;
    r |= (uint32_t)((unsigned)(v.a >> 32)  != 0u) << 1;
    r |= (uint32_t)((unsigned)(v.b)        != 0u) << 2;
    r |= (uint32_t)((unsigned)(v.b >> 32)  != 0u) << 3;
    r |= (uint32_t)((unsigned)(v.c)        != 0u) << 4;
    r |= (uint32_t)((unsigned)(v.c >> 32)  != 0u) << 5;
    r |= (uint32_t)((unsigned)(v.d)        != 0u) << 6;
    r |= (uint32_t)((unsigned)(v.d >> 32)  != 0u) << 7;
    return r;
}

// group barrier over the 16 blocks of graph g (targets 16, then 32)
// release/acquire semantics (no MEMBAR.GPU drain)
__device__ __forceinline__ void group_barrier(int g, unsigned target) {
    __syncthreads();
    if (threadIdx.x == 0) {
        unsigned* addr = &g_bar_grp[g];
        asm volatile("red.release.gpu.global.add.u32 [%0], 1;" :: "l"(addr) : "memory");
        unsigned v;
        do {
            asm volatile("ld.acquire.gpu.global.u32 %0, [%1];" : "=r"(v) : "l"(addr) : "memory");
        } while (v < target);
    }
    __syncthreads();
}

__device__ __forceinline__ void barL() {   // named barrier 1: warps 0..15
    asm volatile("bar.sync 1, 512;" ::: "memory");
}
__device__ __forceinline__ void barU() {   // named barrier 2: warps 16..31
    asm volatile("bar.sync 2, 512;" ::: "memory");
}

__device__ __forceinline__ float warp_sum(float v) {
    #pragma unroll
    for (int o = 16; o; o >>= 1) v += __shfl_down_sync(0xffffffffu, v, o);
    return v;
}

// ---------------------------------------------------------------------------
// ONE kernel, 128 co-resident blocks x 1024 threads; per-graph pipelines.
// ---------------------------------------------------------------------------
__global__ void __launch_bounds__(NTHR) fused_kernel(const float* __restrict__ A,
                                                     float* __restrict__ out) {
    __shared__ uint32_t smask[MPER * NW];   // 32 KB (rowstats)
    __shared__ int      sdeg[MPER];
    __shared__ uint32_t sdegp[MPER / 4];
    __shared__ float    sh[MPER];           // stats (lower warps)
    __shared__ float    r1[16], r2[16], r3[16], r4[16];   // stats (upper warps / f3)
    __shared__ float    bcast;

    int b = blockIdx.x;
    int t = threadIdx.x;
    int warp = t >> 5, lane = t & 31;
    int grp  = b >> 4;          // graph
    int mem  = b & 15;          // member within group
    int lo   = grp << 9;

    // ======================= Phase 0: pack (warp per row) =======================
    {
        int n = b * 32 + warp;                 // rows of graph grp
        long base = (long)n * NNODES + ((long)grp << 9);
        U64x4 v0 = ldg32(A + base + 16 * lane);
        U64x4 v1 = ldg32(A + base + 16 * lane + 8);

        uint32_t h = flags8(v0) | (flags8(v1) << 8);    // 16 bits per lane
        int deg = __popc(h);
        uint32_t w = h | (__shfl_down_sync(0xffffffffu, h, 1) << 16);
        if ((lane & 1) == 0)
            g_mask[n * NW + (lane >> 1)] = w;

        #pragma unroll
        for (int o = 16; o; o >>= 1) deg += __shfl_down_sync(0xffffffffu, deg, o);
        if (lane == 0) g_deg[n] = deg;
    }

    group_barrier(grp, 16);

    // ================= Phase 1: rowstats (warp per row, split halves) =================
    {
        const uint4* src = reinterpret_cast<const uint4*>(&g_mask[lo * NW]);
        uint4*       dst = reinterpret_cast<uint4*>(smask);
        #pragma unroll
        for (int i = 0; i < 2; i++) dst[t + 1024 * i] = src[t + 1024 * i];
        if (t < 512) sdeg[t] = g_deg[lo + t];
        __syncthreads();
        if (t < 128) {
            sdegp[t] = (uint32_t)sdeg[4 * t]
                     | ((uint32_t)sdeg[4 * t + 1] << 8)
                     | ((uint32_t)sdeg[4 * t + 2] << 16)
                     | ((uint32_t)sdeg[4 * t + 3] << 24);
        }
        __syncthreads();

        int l    = lane & 15;            // owned word index
        int half = lane >> 4;            // 0/1: neighbor subset
        int nl   = mem * 32 + warp;      // local row

        uint32_t mw = smask[nl * NW + l];
        uint32_t diagbit = (l == (nl >> 5)) ? (1u << (nl & 31)) : 0u;
        mw |= diagbit;

        uint32_t m2 = 0;
        int f4r = 0;
        int srcbase = half << 3;         // half 0 -> words 0..7, half 1 -> 8..15

        #pragma unroll 1
        for (int w2 = 0; w2 < 8; w2++) {
            uint32_t bits = __shfl_sync(0xffffffffu, mw, srcbase + w2);
            int kb = (srcbase + w2) * 32;
            while (bits) {
                int k = kb + __ffs(bits) - 1;
                bits &= bits - 1;
                uint32_t rk = smask[k * NW + l];
                m2 |= rk;
                f4r += __popc(rk & mw);
            }
        }
        m2 |= __shfl_xor_sync(0xffffffffu, m2, 16);

        int m2cnt = __popc(m2);
        uint32_t aw = mw & ~diagbit;
        int f2num = 0;
        {
            uint32_t bits = aw;
            while (bits) {
                int bb = __ffs(bits) - 1;
                bits &= bits - 1;
                f2num += sdeg[l * 32 + bb];
            }
        }
        int m2deg;
        {
            const uint4* sp4 = reinterpret_cast<const uint4*>(sdegp);
            uint4 q0 = sp4[l * 2], q1 = sp4[l * 2 + 1];
            uint32_t dq[8] = {q0.x, q0.y, q0.z, q0.w, q1.x, q1.y, q1.z, q1.w};
            unsigned acc = 0u;
            #pragma unroll
            for (int j = 0; j < 8; j++) {
                uint32_t spread = (((m2 >> (4 * j)) & 0xFu) * 0x00204081u) & 0x01010101u;
                acc = __dp4a(spread, dq[j], acc);
            }
            m2deg = (int)acc;
        }

        #pragma unroll
        for (int o = 16; o; o >>= 1) f4r += __shfl_down_sync(0xffffffffu, f4r, o);
        #pragma unroll
        for (int o = 8; o; o >>= 1) {
            m2cnt += __shfl_down_sync(0xffffffffu, m2cnt, o, 16);
            m2deg += __shfl_down_sync(0xffffffffu, m2deg, o, 16);
            f2num += __shfl_down_sync(0xffffffffu, f2num, o, 16);
        }

        if (lane == 0) {
            int   n   = lo + nl;
            float deg = (float)sdeg[nl];
            float f1v = 0.0f;
            if (deg > 1.0f) f1v = 2.0f * ((float)f4r - deg) / (deg * (deg - 1.0f));
            float f2v = (deg > 0.0f) ? (float)f2num / deg : 0.0f;
            float f4v = 0.5f * (float)f4r;
            float f5v = (float)m2deg - 2.0f * (float)f4r;
            float f6v = (float)m2cnt - deg - 1.0f;
            g_feat[0 * NNODES + n] = deg;
            g_feat[1 * NNODES + n] = f1v;
            g_feat[2 * NNODES + n] = f2v;
            g_feat[4 * NNODES + n] = f4v;
            g_feat[5 * NNODES + n] = f5v;
            g_feat[6 * NNODES + n] = f6v;
        }
    }

    group_barrier(grp, 32);

    // ====== Phase 2: stats (members 0..6 of each group) ======
    // f != 3: lower warps (0-15) do the median sort; upper warps (16-31) do
    //         mean/moments in parallel on their own named barrier.
    // f == 3: lower warps do everything (f3 gather needs sh), upper warps idle.
    if (mem < 7) {
        int f = mem;

        if (f != 3 && warp >= 16) {
            // ---- upper warps: mean + central moments ----
            int tt = t - 512;
            int wu = warp - 16;
            float x = g_feat[f * NNODES + lo + tt];

            float s = warp_sum(x);
            if (lane == 0) r1[wu] = s;
            barU();
            if (wu == 0) {
                float v = (lane < 16) ? r1[lane] : 0.0f;
                #pragma unroll
                for (int o = 8; o; o >>= 1) v += __shfl_down_sync(0xffffffffu, v, o);
                if (lane == 0) bcast = v * (1.0f / MPER);
            }
            barU();
            float mean = bcast;

            float c  = x - mean;
            float c2 = c * c, c3 = c2 * c, c4 = c2 * c2;
            float s2 = warp_sum(c2), s3 = warp_sum(c3), s4 = warp_sum(c4);
            if (lane == 0) { r2[wu] = s2; r3[wu] = s3; r4[wu] = s4; }
            barU();
            if (wu == 0) {
                float v2 = (lane < 16) ? r2[lane] : 0.0f;
                float v3 = (lane < 16) ? r3[lane] : 0.0f;
                float v4 = (lane < 16) ? r4[lane] : 0.0f;
                #pragma unroll
                for (int o = 8; o; o >>= 1) {
                    v2 += __shfl_down_sync(0xffffffffu, v2, o);
                    v3 += __shfl_down_sync(0xffffffffu, v3, o);
                    v4 += __shfl_down_sync(0xffffffffu, v4, o);
                }
                if (lane == 0) {
                    float m2 = v2 * (1.0f / MPER);
                    float m3 = v3 * (1.0f / MPER);
                    float m4 = v4 * (1.0f / MPER);
                    float eps = 1e-4f;
                    float sd   = sqrtf(m2);
                    float skew = m3 / fmaxf(m2 * sd, eps);
                    float kurt = m4 / fmaxf(m2 * m2, eps);
                    out[grp * 35 +  0 + f] = mean;
                    out[grp * 35 + 14 + f] = sd;
                    out[grp * 35 + 21 + f] = skew;
                    out[grp * 35 + 28 + f] = kurt;
                }
            }
        } else if (f != 3 && warp < 16) {
            // ---- lower warps: median only (hybrid bitonic) ----
            float x = g_feat[f * NNODES + lo + t];
            #pragma unroll 1
            for (int k = 2; k <= MPER; k <<= 1) {
                bool dirUp = ((t & k) == 0);
                #pragma unroll 1
                for (int j = k >> 1; j >= 32; j >>= 1) {
                    barL();
                    sh[t] = x;
                    barL();
                    float other = sh[t ^ j];
                    bool amLow = ((t & j) == 0);
                    x = (dirUp == amLow) ? fminf(x, other) : fmaxf(x, other);
                }
                int j0 = (k >> 1 < 16) ? (k >> 1) : 16;
                #pragma unroll 1
                for (int j = j0; j >= 1; j >>= 1) {
                    float other = __shfl_xor_sync(0xffffffffu, x, j);
                    bool amLow = ((t & j) == 0);
                    x = (dirUp == amLow) ? fminf(x, other) : fmaxf(x, other);
                }
            }
            if (t == (MPER - 1) / 2) out[grp * 35 + 7 + f] = x;
        } else if (f == 3 && warp < 16) {
            // ---- f3: full pipeline in lower warps ----
            sh[t] = g_feat[1 * NNODES + lo + t];
            barL();
            int n = lo + t;
            float s = 0.0f;
            const uint4* rm = reinterpret_cast<const uint4*>(&g_mask[n * NW]);
            #pragma unroll
            for (int q = 0; q < 4; q++) {
                uint4 u = rm[q];
                uint32_t ws[4] = {u.x, u.y, u.z, u.w};
                #pragma unroll
                for (int j = 0; j < 4; j++) {
                    uint32_t bits = ws[j];
                    int base = (q * 4 + j) * 32;
                    while (bits) {
                        int v = base + __ffs(bits) - 1;
                        bits &= bits - 1;
                        s += sh[v];
                    }
                }
            }
            float deg = (float)g_deg[n];
            float x = (deg > 0.0f) ? s / deg : 0.0f;
            barL();

            // mean
            float s1 = warp_sum(x);
            if (lane == 0) r1[warp] = s1;
            barL();
            if (warp == 0) {
                float v = (lane < 16) ? r1[lane] : 0.0f;
                #pragma unroll
                for (int o = 8; o; o >>= 1) v += __shfl_down_sync(0xffffffffu, v, o);
                if (lane == 0) bcast = v * (1.0f / MPER);
            }
            barL();
            float mean = bcast;

            float c  = x - mean;
            float c2 = c * c, c3 = c2 * c, c4 = c2 * c2;
            float s2 = warp_sum(c2), s3 = warp_sum(c3), s4 = warp_sum(c4);
            if (lane == 0) { r2[warp] = s2; r3[warp] = s3; r4[warp] = s4; }
            barL();
            if (warp == 0) {
                float v2 = (lane < 16) ? r2[lane] : 0.0f;
                float v3 = (lane < 16) ? r3[lane] : 0.0f;
                float v4 = (lane < 16) ? r4[lane] : 0.0f;
                #pragma unroll
                for (int o = 8; o; o >>= 1) {
                    v2 += __shfl_down_sync(0xffffffffu, v2, o);
                    v3 += __shfl_down_sync(0xffffffffu, v3, o);
                    v4 += __shfl_down_sync(0xffffffffu, v4, o);
                }
                if (lane == 0) {
                    float m2 = v2 * (1.0f / MPER);
                    float m3 = v3 * (1.0f / MPER);
                    float m4 = v4 * (1.0f / MPER);
                    float eps = 1e-4f;
                    float sd   = sqrtf(m2);
                    float skew = m3 / fmaxf(m2 * sd, eps);
                    float kurt = m4 / fmaxf(m2 * m2, eps);
                    out[grp * 35 +  0 + f] = mean;
                    out[grp * 35 + 14 + f] = sd;
                    out[grp * 35 + 21 + f] = skew;
                    out[grp * 35 + 28 + f] = kurt;
                }
            }

            // median
            #pragma unroll 1
            for (int k = 2; k <= MPER; k <<= 1) {
                bool dirUp = ((t & k) == 0);
                #pragma unroll 1
                for (int j = k >> 1; j >= 32; j >>= 1) {
                    barL();
                    sh[t] = x;
                    barL();
                    float other = sh[t ^ j];
                    bool amLow = ((t & j) == 0);
                    x = (dirUp == amLow) ? fminf(x, other) : fmaxf(x, other);
                }
                int j0 = (k >> 1 < 16) ? (k >> 1) : 16;
                #pragma unroll 1
                for (int j = j0; j >= 1; j >>= 1) {
                    float other = __shfl_xor_sync(0xffffffffu, x, j);
                    bool amLow = ((t & j) == 0);
                    x = (dirUp == amLow) ? fminf(x, other) : fmaxf(x, other);
                }
            }
            if (t == (MPER - 1) / 2) out[grp * 35 + 7 + f] = x;
        }
    }

    // ======================= Exit: reset barrier state =======================
    __syncthreads();   // barrier 0: all 32 warps
    if (t == 0) {
        unsigned v = atomicAdd(&g_exit, 1u);
        if (v == NBLK - 1) {                 // last block out resets for next launch
            #pragma unroll
            for (int i = 0; i < NG; i++) *(volatile unsigned*)&g_bar_grp[i] = 0u;
            *(volatile unsigned*)&g_exit = 0u;
            __threadfence();
        }
    }
}

// ---------------------------------------------------------------------------
extern "C" void kernel_launch(void* const* d_in, const int* in_sizes, int n_in,
                              void* d_out, int out_size) {
    const float* A = (const float*)d_in[0];
    float* out = (float*)d_out;
    fused_kernel<<<NBLK, NTHR>>>(A, out);
}